// round 16
// baseline (speedup 1.0000x reference)
#include <cuda_runtime.h>
#include <stdint.h>

// Kaldi LinearResample 16000 -> 14400, LPF_WIDTH=6 (polyphase, up=9, stride=10).
//   out[b, 9k+i] = sum_m w[i][m] * x[b, 10k + fi[i] + m],  x zero-padded outside [0,T)
//   121 nonzero taps baked as compile-time float literals -> FFMA-imm.
// Both DRAM streams via 1D TMA bulk. TILE_K=192: small work quantum (16000 tiles,
// 1036 CTAs, 7/SM) -> ~4x smaller straggler tail than TILE_K=384, more concurrent
// TMA streams; bursts (7744B read / 6912B write) still full-page.

#define T_IN        480000
#define TOT_K       48000
#define UP          9
#define TOT_OUT     (TOT_K * UP)
#define TILE_K      192
#define NTHREADS    192
#define TILE_F      1936          // 10*191 + 22 + shift(<=2); 7744 B (16B multiple)
#define OS_F        (TILE_K * UP) // 1728 floats = 6912 B, contiguous in gmem
#define TILES_PER_ROW 250         // 48000 / 192 exactly -> every tile full
#define NCTA        1036          // 148 SM * 7 CTAs, persistent

// ---------------- compile-time weight table ----------------
constexpr double KPI = 3.14159265358979323846264338327950288;

constexpr double tsin(double x) {
    while (x >  KPI) x -= 2.0 * KPI;
    while (x < -KPI) x += 2.0 * KPI;
    double x2 = x * x, term = x, s = x;
    for (int k = 1; k <= 16; ++k) {
        term *= -x2 / (double)((2 * k) * (2 * k + 1));
        s += term;
    }
    return s;
}
constexpr double tcos(double x) { return tsin(KPI * 0.5 - x); }

struct WTab { float w[9][14]; };
constexpr WTab make_wtab() {
    WTab t{};
    constexpr int FI[9] = {-6, -5, -4, -3, -2, -1, 0, 2, 3};
    for (int i = 0; i < 9; ++i)
        for (int m = 0; m < 14; ++m) {
            int n = 9 * (FI[i] + m) - 10 * i;
            int an = n < 0 ? -n : n;
            double v = 0.0;
            if (an == 0)      v = 0.891;            // 2*lowpass_cutoff/orig_freq
            else if (an <= 60)
                v = (1.0 + tcos(0.0165 * KPI * an)) * tsin(0.099 * KPI * an)
                    * 9.0 / (2.0 * KPI * an);
            t.w[i][m] = (float)v;
        }
    return t;
}
__device__ constexpr WTab WT = make_wtab();

// ---------------- TMA 1D bulk load/store + mbarrier ----------------
__device__ __forceinline__ void bulk_load(float* sdst, const float* gsrc, int bytes,
                                          unsigned mbar) {
    unsigned saddr = (unsigned)__cvta_generic_to_shared(sdst);
    asm volatile(
        "cp.async.bulk.shared::cta.global.mbarrier::complete_tx::bytes [%0], [%1], %2, [%3];"
        :: "r"(saddr), "l"(gsrc), "r"(bytes), "r"(mbar) : "memory");
}
__device__ __forceinline__ void bulk_store(float* gdst, const float* ssrc, int bytes) {
    unsigned saddr = (unsigned)__cvta_generic_to_shared(ssrc);
    asm volatile("cp.async.bulk.global.shared::cta.bulk_group [%0], [%1], %2;"
                 :: "l"(gdst), "r"(saddr), "r"(bytes) : "memory");
}
#define BULK_COMMIT() asm volatile("cp.async.bulk.commit_group;" ::: "memory")
#define BULK_WAIT1()  asm volatile("cp.async.bulk.wait_group.read 1;" ::: "memory")
#define FENCE_ASYNC() asm volatile("fence.proxy.async.shared::cta;" ::: "memory")

__device__ __forceinline__ void mbar_init(unsigned mbar, unsigned cnt) {
    asm volatile("mbarrier.init.shared.b64 [%0], %1;" :: "r"(mbar), "r"(cnt) : "memory");
}
__device__ __forceinline__ void mbar_expect_tx(unsigned mbar, unsigned bytes) {
    asm volatile("mbarrier.arrive.expect_tx.shared.b64 _, [%0], %1;"
                 :: "r"(mbar), "r"(bytes) : "memory");
}
__device__ __forceinline__ void mbar_wait(unsigned mbar, unsigned parity) {
    asm volatile(
        "{\n\t.reg .pred P;\n\t"
        "WAIT_%=:\n\t"
        "mbarrier.try_wait.parity.acquire.cta.shared::cta.b64 P, [%0], %1, 0x989680;\n\t"
        "@P bra.uni DONE_%=;\n\t"
        "bra.uni WAIT_%=;\n\t"
        "DONE_%=:\n\t}"
        :: "r"(mbar), "r"(parity) : "memory");
}

// ---------------- staging: TMA for interior, scalar for edge ----------------
// returns true if edge tile (scalar path used, no mbarrier tx)
__device__ __forceinline__ bool stage_tile(float* xs, const float* __restrict__ in,
                                           int t, unsigned mbar) {
    const int b  = t / TILES_PER_ROW;
    const int kt = (t - b * TILES_PER_ROW) * TILE_K;
    const float* rowin = in + (size_t)b * T_IN;
    const int gstart = 10 * kt - 6;
    const int g4 = gstart & ~3;

    if (g4 >= 0 && g4 + TILE_F <= T_IN) {
        if (threadIdx.x == 0) {
            mbar_expect_tx(mbar, TILE_F * 4);
            bulk_load(xs, rowin + g4, TILE_F * 4, mbar);
        }
        return false;
    }
    // edge tile (2 per row): guarded scalar path with zero padding
    for (int v = threadIdx.x; v < TILE_F / 4; v += NTHREADS) {
        int g = g4 + 4 * v;
        float4 val;
        if (g >= 0 && g <= T_IN - 4) {
            val = *reinterpret_cast<const float4*>(rowin + g);
        } else {
            val.x = (g + 0 >= 0 && g + 0 < T_IN) ? rowin[g + 0] : 0.0f;
            val.y = (g + 1 >= 0 && g + 1 < T_IN) ? rowin[g + 1] : 0.0f;
            val.z = (g + 2 >= 0 && g + 2 < T_IN) ? rowin[g + 2] : 0.0f;
            val.w = (g + 3 >= 0 && g + 3 < T_IN) ? rowin[g + 3] : 0.0f;
        }
        *reinterpret_cast<float4*>(xs + 4 * v) = val;
    }
    return true;
}

__global__ __launch_bounds__(NTHREADS, 7)
void sp_resample_kernel(const float* __restrict__ in, float* __restrict__ out,
                        int ntiles) {
    __shared__ float xs[2][TILE_F];
    __shared__ float os[2][OS_F];              // double-buffered output tile
    __shared__ __align__(8) unsigned long long mbar_s[2];

    const int tid  = threadIdx.x;
    const int stride = gridDim.x;
    const unsigned mb0 = (unsigned)__cvta_generic_to_shared(&mbar_s[0]);
    const unsigned mb1 = (unsigned)__cvta_generic_to_shared(&mbar_s[1]);

    if (tid == 0) { mbar_init(mb0, 1); mbar_init(mb1, 1); }
    __syncthreads();

    unsigned phase[2] = {0, 0};
    bool edge_cur = false, edge_next = false;

    int t0 = blockIdx.x;
    if (t0 < ntiles) edge_cur = stage_tile(xs[0], in, t0, mb0);

    int cur = 0;
    for (int t = t0; t < ntiles; t += stride) {
        // loop-top sync: all compute reads of xs[1-cur] (2 tiles ago) done, and
        // tid0's BULK_WAIT1 (os reads) published
        __syncthreads();
        int tn = t + stride;
        if (tn < ntiles)
            edge_next = stage_tile(xs[1 - cur], in, tn, cur ? mb0 : mb1);

        // wait for xs[cur]
        if (!edge_cur) {
            mbar_wait(cur ? mb1 : mb0, phase[cur]);
            phase[cur] ^= 1;
        }
        __syncthreads();                       // edge-path STS visibility + uniformity

        const int b  = t / TILES_PER_ROW;
        const int kt = (t - b * TILES_PER_ROW) * TILE_K;
        const int gstart = 10 * kt - 6;
        const int shift  = gstart & 3;                 // 0 or 2 (gstart even)
        const float* xb = xs[cur];
        float* ow = os[cur];

        {
            float2 xr2[11];
            const int w0 = 10 * tid + shift;           // even -> aligned float2
#pragma unroll
            for (int c = 0; c < 11; ++c)
                xr2[c] = *reinterpret_cast<const float2*>(xb + w0 + 2 * c);
#define XR(c) (((c) & 1) ? xr2[(c) >> 1].y : xr2[(c) >> 1].x)

            constexpr int FI6[9] = {0, 1, 2, 3, 4, 5, 6, 8, 9};
            constexpr int N0[9]  = {-54, -55, -56, -57, -58, -59, -60, -52, -53};
#pragma unroll
            for (int i = 0; i < 9; ++i) {
                float acc = 0.0f;
#pragma unroll
                for (int m = 0; m < 14; ++m) {
                    const int n  = N0[i] + 9 * m;
                    const int an = (n < 0) ? -n : n;
                    if (an <= 60) {                    // pruned at compile time
                        acc = fmaf(WT.w[i][m], XR(FI6[i] + m), acc);
                    }
                }
                ow[9 * tid + i] = acc;
            }
#undef XR
        }
        __syncthreads();                       // all STS to os[cur] done

        if (tid == 0) {
            FENCE_ASYNC();                     // order STS -> async proxy
            bulk_store(out + (size_t)b * TOT_OUT + (size_t)9 * kt, ow, OS_F * 4);
            BULK_COMMIT();
            BULK_WAIT1();                      // <=1 bulk store in flight
        }
        edge_cur = edge_next;
        cur ^= 1;
    }
    if (tid == 0) asm volatile("cp.async.bulk.wait_group.read 0;" ::: "memory");
}

extern "C" void kernel_launch(void* const* d_in, const int* in_sizes, int n_in,
                              void* d_out, int out_size) {
    const float* in = (const float*)d_in[0];
    float* out = (float*)d_out;
    const int B = in_sizes[0] / T_IN;
    const int ntiles = B * TILES_PER_ROW;
    sp_resample_kernel<<<NCTA, NTHREADS>>>(in, out, ntiles);
}

// round 17
// speedup vs baseline: 1.0556x; 1.0556x over previous
#include <cuda_runtime.h>
#include <stdint.h>

// Kaldi LinearResample 16000 -> 14400, LPF_WIDTH=6 (polyphase, up=9, stride=10).
//   out[b, 9k+i] = sum_m w[i][m] * x[b, 10k + fi[i] + m],  x zero-padded outside [0,T)
//   121 nonzero taps baked as compile-time float literals -> FFMA-imm.
// Both DRAM streams via 1D TMA bulk. This round: triple-buffered output tile with
// wait_group.read 2 -> two 13824B stores in flight per CTA (write stream never gaps).

#define T_IN        480000
#define TOT_K       48000
#define UP          9
#define TOT_OUT     (TOT_K * UP)
#define TILE_K      384
#define NTHREADS    384
#define TILE_F      3856          // 10*383 + 22 + shift(<=2); 15424 B (16B multiple)
#define OS_F        (TILE_K * UP) // 3456 floats = 13824 B, contiguous in gmem
#define TILES_PER_ROW 125         // 48000 / 384 exactly -> every tile full
#define NCTA        444           // 148 SM * 3 CTAs, persistent

// ---------------- compile-time weight table ----------------
constexpr double KPI = 3.14159265358979323846264338327950288;

constexpr double tsin(double x) {
    while (x >  KPI) x -= 2.0 * KPI;
    while (x < -KPI) x += 2.0 * KPI;
    double x2 = x * x, term = x, s = x;
    for (int k = 1; k <= 16; ++k) {
        term *= -x2 / (double)((2 * k) * (2 * k + 1));
        s += term;
    }
    return s;
}
constexpr double tcos(double x) { return tsin(KPI * 0.5 - x); }

struct WTab { float w[9][14]; };
constexpr WTab make_wtab() {
    WTab t{};
    constexpr int FI[9] = {-6, -5, -4, -3, -2, -1, 0, 2, 3};
    for (int i = 0; i < 9; ++i)
        for (int m = 0; m < 14; ++m) {
            int n = 9 * (FI[i] + m) - 10 * i;
            int an = n < 0 ? -n : n;
            double v = 0.0;
            if (an == 0)      v = 0.891;            // 2*lowpass_cutoff/orig_freq
            else if (an <= 60)
                v = (1.0 + tcos(0.0165 * KPI * an)) * tsin(0.099 * KPI * an)
                    * 9.0 / (2.0 * KPI * an);
            t.w[i][m] = (float)v;
        }
    return t;
}
__device__ constexpr WTab WT = make_wtab();

// ---------------- TMA 1D bulk load/store + mbarrier ----------------
__device__ __forceinline__ void bulk_load(float* sdst, const float* gsrc, int bytes,
                                          unsigned mbar) {
    unsigned saddr = (unsigned)__cvta_generic_to_shared(sdst);
    asm volatile(
        "cp.async.bulk.shared::cta.global.mbarrier::complete_tx::bytes [%0], [%1], %2, [%3];"
        :: "r"(saddr), "l"(gsrc), "r"(bytes), "r"(mbar) : "memory");
}
__device__ __forceinline__ void bulk_store(float* gdst, const float* ssrc, int bytes) {
    unsigned saddr = (unsigned)__cvta_generic_to_shared(ssrc);
    asm volatile("cp.async.bulk.global.shared::cta.bulk_group [%0], [%1], %2;"
                 :: "l"(gdst), "r"(saddr), "r"(bytes) : "memory");
}
#define BULK_COMMIT() asm volatile("cp.async.bulk.commit_group;" ::: "memory")
#define BULK_WAIT2()  asm volatile("cp.async.bulk.wait_group.read 2;" ::: "memory")
#define FENCE_ASYNC() asm volatile("fence.proxy.async.shared::cta;" ::: "memory")

__device__ __forceinline__ void mbar_init(unsigned mbar, unsigned cnt) {
    asm volatile("mbarrier.init.shared.b64 [%0], %1;" :: "r"(mbar), "r"(cnt) : "memory");
}
__device__ __forceinline__ void mbar_expect_tx(unsigned mbar, unsigned bytes) {
    asm volatile("mbarrier.arrive.expect_tx.shared.b64 _, [%0], %1;"
                 :: "r"(mbar), "r"(bytes) : "memory");
}
__device__ __forceinline__ void mbar_wait(unsigned mbar, unsigned parity) {
    asm volatile(
        "{\n\t.reg .pred P;\n\t"
        "WAIT_%=:\n\t"
        "mbarrier.try_wait.parity.acquire.cta.shared::cta.b64 P, [%0], %1, 0x989680;\n\t"
        "@P bra.uni DONE_%=;\n\t"
        "bra.uni WAIT_%=;\n\t"
        "DONE_%=:\n\t}"
        :: "r"(mbar), "r"(parity) : "memory");
}

// ---------------- staging: TMA for interior, scalar for edge ----------------
// returns true if edge tile (scalar path used, no mbarrier tx)
__device__ __forceinline__ bool stage_tile(float* xs, const float* __restrict__ in,
                                           int t, unsigned mbar) {
    const int b  = t / TILES_PER_ROW;
    const int kt = (t - b * TILES_PER_ROW) * TILE_K;
    const float* rowin = in + (size_t)b * T_IN;
    const int gstart = 10 * kt - 6;
    const int g4 = gstart & ~3;

    if (g4 >= 0 && g4 + TILE_F <= T_IN) {
        if (threadIdx.x == 0) {
            mbar_expect_tx(mbar, TILE_F * 4);
            bulk_load(xs, rowin + g4, TILE_F * 4, mbar);
        }
        return false;
    }
    // edge tile (2 per row): guarded scalar path with zero padding
    for (int v = threadIdx.x; v < TILE_F / 4; v += NTHREADS) {
        int g = g4 + 4 * v;
        float4 val;
        if (g >= 0 && g <= T_IN - 4) {
            val = *reinterpret_cast<const float4*>(rowin + g);
        } else {
            val.x = (g + 0 >= 0 && g + 0 < T_IN) ? rowin[g + 0] : 0.0f;
            val.y = (g + 1 >= 0 && g + 1 < T_IN) ? rowin[g + 1] : 0.0f;
            val.z = (g + 2 >= 0 && g + 2 < T_IN) ? rowin[g + 2] : 0.0f;
            val.w = (g + 3 >= 0 && g + 3 < T_IN) ? rowin[g + 3] : 0.0f;
        }
        *reinterpret_cast<float4*>(xs + 4 * v) = val;
    }
    return true;
}

__global__ __launch_bounds__(NTHREADS, 3)
void sp_resample_kernel(const float* __restrict__ in, float* __restrict__ out,
                        int ntiles) {
    __shared__ float xs[2][TILE_F];
    __shared__ float os[3][OS_F];              // triple-buffered output tile
    __shared__ __align__(8) unsigned long long mbar_s[2];

    const int tid  = threadIdx.x;
    const int stride = gridDim.x;
    const unsigned mb0 = (unsigned)__cvta_generic_to_shared(&mbar_s[0]);
    const unsigned mb1 = (unsigned)__cvta_generic_to_shared(&mbar_s[1]);

    if (tid == 0) { mbar_init(mb0, 1); mbar_init(mb1, 1); }
    __syncthreads();

    unsigned phase[2] = {0, 0};
    bool edge_cur = false, edge_next = false;

    int t0 = blockIdx.x;
    if (t0 < ntiles) edge_cur = stage_tile(xs[0], in, t0, mb0);

    int cur = 0;                               // xs buffer (0/1)
    int sb  = 0;                               // os buffer (0/1/2)
    for (int t = t0; t < ntiles; t += stride) {
        // loop-top sync: publishes tid0's BULK_WAIT2 from last iteration, i.e. the
        // store that read os[sb] three tiles ago has retired its smem reads; also
        // all compute reads of xs[1-cur] (2 tiles ago) are done.
        __syncthreads();
        int tn = t + stride;
        if (tn < ntiles)
            edge_next = stage_tile(xs[1 - cur], in, tn, cur ? mb0 : mb1);

        // wait for xs[cur]
        if (!edge_cur) {
            mbar_wait(cur ? mb1 : mb0, phase[cur]);
            phase[cur] ^= 1;
        }
        __syncthreads();                       // edge-path STS visibility + uniformity

        const int b  = t / TILES_PER_ROW;
        const int kt = (t - b * TILES_PER_ROW) * TILE_K;
        const int gstart = 10 * kt - 6;
        const int shift  = gstart & 3;                 // 0 or 2 (gstart even)
        const float* xb = xs[cur];
        float* ow = os[sb];

        {
            float2 xr2[11];
            const int w0 = 10 * tid + shift;           // even -> aligned float2
#pragma unroll
            for (int c = 0; c < 11; ++c)
                xr2[c] = *reinterpret_cast<const float2*>(xb + w0 + 2 * c);
#define XR(c) (((c) & 1) ? xr2[(c) >> 1].y : xr2[(c) >> 1].x)

            constexpr int FI6[9] = {0, 1, 2, 3, 4, 5, 6, 8, 9};
            constexpr int N0[9]  = {-54, -55, -56, -57, -58, -59, -60, -52, -53};
#pragma unroll
            for (int i = 0; i < 9; ++i) {
                float acc = 0.0f;
#pragma unroll
                for (int m = 0; m < 14; ++m) {
                    const int n  = N0[i] + 9 * m;
                    const int an = (n < 0) ? -n : n;
                    if (an <= 60) {                    // pruned at compile time
                        acc = fmaf(WT.w[i][m], XR(FI6[i] + m), acc);
                    }
                }
                ow[9 * tid + i] = acc;
            }
#undef XR
        }
        __syncthreads();                       // all STS to os[sb] done

        if (tid == 0) {
            FENCE_ASYNC();                     // order STS -> async proxy
            bulk_store(out + (size_t)b * TOT_OUT + (size_t)9 * kt, ow, OS_F * 4);
            BULK_COMMIT();
            BULK_WAIT2();                      // <=2 bulk stores in flight
        }
        edge_cur = edge_next;
        cur ^= 1;
        sb = (sb + 1) % 3;
    }
    if (tid == 0) asm volatile("cp.async.bulk.wait_group.read 0;" ::: "memory");
}

extern "C" void kernel_launch(void* const* d_in, const int* in_sizes, int n_in,
                              void* d_out, int out_size) {
    const float* in = (const float*)d_in[0];
    float* out = (float*)d_out;
    const int B = in_sizes[0] / T_IN;
    const int ntiles = B * TILES_PER_ROW;
    sp_resample_kernel<<<NCTA, NTHREADS>>>(in, out, ntiles);
}